// round 14
// baseline (speedup 1.0000x reference)
#include <cuda_runtime.h>
#include <cstdint>

// out_half[h] = X[idx[h], :]  (h = e*2+half, 512B per half-row)
// 256-bit (v8.b32) loads+stores: 16 lanes cover one 512B half-row (32B/lane).
// CPT=8 granules/thread (256B in flight per thread) + relaxed reg budget:
// deeper per-warp read queue so the DRAM controller can reorder the random
// read stream around the linear write stream. Gathers: .L2::evict_last
// (direct v8 modifier). Stores: evict-first policy.

#define CPT 8

struct V8 { unsigned r0,r1,r2,r3,r4,r5,r6,r7; };

__device__ __forceinline__ uint64_t make_evict_first_policy() {
    uint64_t pol;
    asm("createpolicy.fractional.L2::evict_first.b64 %0, 1.0;" : "=l"(pol));
    return pol;
}

__device__ __forceinline__ V8 ldg_v8_el(const void* p) {
    V8 v;
    asm("ld.global.nc.L2::evict_last.v8.b32 {%0,%1,%2,%3,%4,%5,%6,%7}, [%8];"
        : "=r"(v.r0), "=r"(v.r1), "=r"(v.r2), "=r"(v.r3),
          "=r"(v.r4), "=r"(v.r5), "=r"(v.r6), "=r"(v.r7)
        : "l"(p));
    return v;
}

__device__ __forceinline__ void stg_v8_ef(void* p, const V8& v, uint64_t pol) {
    asm volatile("st.global.L2::cache_hint.v8.b32 [%0], {%1,%2,%3,%4,%5,%6,%7,%8}, %9;"
        :: "l"(p),
           "r"(v.r0), "r"(v.r1), "r"(v.r2), "r"(v.r3),
           "r"(v.r4), "r"(v.r5), "r"(v.r6), "r"(v.r7),
           "l"(pol)
        : "memory");
}

__global__ void __launch_bounds__(256, 1) link_embed_gather_kernel(
    const char* __restrict__ Xb,        // byte pointer to X
    const int* __restrict__ idx,        // flat [2E] node ids (== [E,2] layout)
    char* __restrict__ outb,            // byte pointer to out
    int total_granules)                 // 2E * 16 (one 32B granule each)
{
    const int stride = gridDim.x * blockDim.x;
    const int t0 = blockIdx.x * blockDim.x + threadIdx.x;
    const uint64_t pol = make_evict_first_policy();

    if (t0 + (CPT - 1) * stride < total_granules) {
        // ---- fast path (exact at bench shape) ----
        unsigned off[CPT];
        #pragma unroll
        for (int i = 0; i < CPT; i++) {
            int t = t0 + i * stride;
            int h = t >> 4;                       // half-row id
            int node = __ldg(&idx[h]);            // uniform over 16 lanes
            off[i] = ((unsigned)node << 9) | ((unsigned)(t & 15) << 5);
        }

        V8 v[CPT];
        #pragma unroll
        for (int i = 0; i < CPT; i++)
            v[i] = ldg_v8_el(Xb + off[i]);        // 8 gathers in flight

        #pragma unroll
        for (int i = 0; i < CPT; i++)
            stg_v8_ef(outb + (size_t)(t0 + i * stride) * 32, v[i], pol);
    } else {
        // ---- guarded tail (not taken at bench shape) ----
        #pragma unroll
        for (int i = 0; i < CPT; i++) {
            int t = t0 + i * stride;
            if (t < total_granules) {
                int h = t >> 4;
                int node = __ldg(&idx[h]);
                unsigned off = ((unsigned)node << 9) | ((unsigned)(t & 15) << 5);
                V8 v = ldg_v8_el(Xb + off);
                stg_v8_ef(outb + (size_t)t * 32, v, pol);
            }
        }
    }
}

extern "C" void kernel_launch(void* const* d_in, const int* in_sizes, int n_in,
                              void* d_out, int out_size)
{
    const char* Xb = (const char*)d_in[0];
    const int* idx = (const int*)d_in[1];
    char* outb = (char*)d_out;

    int H = in_sizes[1];                 // 2E half-rows
    int total_granules = H * 16;         // 32B granules

    int threads = 256;
    int per_block = threads * CPT;
    int blocks = (total_granules + per_block - 1) / per_block;
    link_embed_gather_kernel<<<blocks, threads>>>(Xb, idx, outb, total_granules);
}